// round 15
// baseline (speedup 1.0000x reference)
#include <cuda_runtime.h>
#include <math.h>
#include <stdint.h>

#define NN  50000
#define FF  256
#define HH  128
#define CC  16
#define HXD 64
#define EE  500000

// ---------------- scratch (device globals; no allocation allowed) ----------------
__device__ float g_xw1 [(size_t)NN * HH];   // x @ W1
__device__ float g_xe  [(size_t)NN * HXD];  // relu(x @ Wx + bx)
__device__ float g_agg1[(size_t)NN * HH];   // layer-1 aggregate (relu fused into GEMM2 load)
__device__ float g_xw2 [(size_t)NN * CC];   // h @ W2
__device__ float g_agg2[(size_t)NN * CC];   // layer-2 aggregate = logits
__device__ int   g_cnt [NN];                // in-degree (excl self-loop)
__device__ int   g_fill[NN];
__device__ int   g_off [NN + 1];            // CSR offsets
__device__ int2  g_csr [EE];                // dst-sorted (src, norm-bits)
__device__ int   g_csrd[EE];                // dst per sorted edge
__device__ float g_u   [NN];
__device__ float g_v   [NN];
__device__ int   g_maskkind;                // 0=int32, 1=float32, 2=byte/bool

// ---------------- prep: zero cnt/fill + train_mask dtype detection ----------------
__global__ void prep_kernel(const unsigned* __restrict__ tm) {
    int i = blockIdx.x * blockDim.x + threadIdx.x;
    if (i < NN) { g_cnt[i] = 0; g_fill[i] = 0; }
    if (blockIdx.x == 0) {
        __shared__ int bad_int, bad_float;
        if (threadIdx.x == 0) { bad_int = 0; bad_float = 0; }
        __syncthreads();
        for (int j = threadIdx.x; j < 2048; j += blockDim.x) {
            unsigned vv = tm[j];
            if (vv > 1u) bad_int = 1;                          // benign write race
            if (vv != 0u && vv != 0x3F800000u) bad_float = 1;
        }
        __syncthreads();
        if (threadIdx.x == 0)
            g_maskkind = (bad_int == 0) ? 0 : ((bad_float == 0) ? 1 : 2);
    }
}

__global__ void deg_count_kernel(const int* __restrict__ dst) {
    int e = blockIdx.x * blockDim.x + threadIdx.x;
    if (e < EE) atomicAdd(&g_cnt[dst[e]], 1);
}

// single-block exclusive scan of g_cnt -> g_off
__global__ void csr_scan_kernel() {
    const int T2 = 1024;
    const int C = (NN + T2 - 1) / T2;
    __shared__ int part[T2];
    int t = threadIdx.x;
    int base = t * C;
    int s = 0;
    for (int i = 0; i < C; i++) {
        int idx = base + i;
        if (idx < NN) s += g_cnt[idx];
    }
    part[t] = s;
    __syncthreads();
    for (int o = 1; o < T2; o <<= 1) {
        int v = (t >= o) ? part[t - o] : 0;
        __syncthreads();
        part[t] += v;
        __syncthreads();
    }
    int run = part[t] - s;           // exclusive prefix of this chunk
    for (int i = 0; i < C; i++) {
        int idx = base + i;
        if (idx < NN) { g_off[idx] = run; run += g_cnt[idx]; }
    }
    if (t == T2 - 1) g_off[NN] = run;
}

__global__ void csr_fill_kernel(const int* __restrict__ src, const int* __restrict__ dst) {
    int e = blockIdx.x * blockDim.x + threadIdx.x;
    if (e >= EE) return;
    int s = __ldg(&src[e]);
    int d = __ldg(&dst[e]);
    float nm = rsqrtf((float)(g_cnt[s] + 1)) * rsqrtf((float)(g_cnt[d] + 1));
    int pos = g_off[d] + atomicAdd(&g_fill[d], 1);
    g_csr[pos] = make_int2(s, __float_as_int(nm));
    g_csrd[pos] = d;
}

// ================= fused 3xBF16 tensor-core GEMM (R8 config): [xw1 | xe] = x @ [W1 | Wx] =================
#define BMT 128
#define BNT 64
#define BKT 32
#define ARL 20
#define BRL 72
#define A_SZ (BMT * ARL)
#define B_SZ ((BKT / 2) * BRL)
#define BUF_SZ (2 * A_SZ + 2 * B_SZ)
#define SMEM_BYTES (2 * BUF_SZ * 4)

__device__ __forceinline__ void splitpack(float e, float o, uint32_t& hp, uint32_t& lp) {
    asm("cvt.rn.bf16x2.f32 %0, %1, %2;" : "=r"(hp) : "f"(o), "f"(e));
    float he = __uint_as_float(hp << 16);
    float ho = __uint_as_float(hp & 0xFFFF0000u);
    float le = e - he, lo = o - ho;
    asm("cvt.rn.bf16x2.f32 %0, %1, %2;" : "=r"(lp) : "f"(lo), "f"(le));
}

__device__ __forceinline__ void mma_bf16(float* c, const uint32_t* a, const uint32_t* b) {
    asm volatile(
        "mma.sync.aligned.m16n8k16.row.col.f32.bf16.bf16.f32 "
        "{%0,%1,%2,%3}, {%4,%5,%6,%7}, {%8,%9}, {%0,%1,%2,%3};"
        : "+f"(c[0]), "+f"(c[1]), "+f"(c[2]), "+f"(c[3])
        : "r"(a[0]), "r"(a[1]), "r"(a[2]), "r"(a[3]), "r"(b[0]), "r"(b[1]));
}

__global__ __launch_bounds__(256, 2)
void bf16_fused_gemm_kernel(const float* __restrict__ A,
                            const float* __restrict__ W1,
                            const float* __restrict__ Wx,
                            const float* __restrict__ bx,
                            float* __restrict__ Cxw1,
                            float* __restrict__ Cxe,
                            int M) {
    extern __shared__ uint32_t sm[];

    const int tid = threadIdx.x;
    const int rowBase = blockIdx.y * BMT;
    const bool isXe = (blockIdx.x == 2);
    const float* Bsrc = isXe ? Wx : W1;
    const int Bstride = isXe ? HXD : HH;
    const int colOff = isXe ? 0 : blockIdx.x * BNT;

    const int warp = tid >> 5, lane = tid & 31;
    const int wm = warp >> 1, wn = warp & 1;
    const int lr = lane >> 2, lc = lane & 3;

    float4 aSt[4];
    float2 bSt0[2], bSt1[2];

    auto loadStage = [&](int k0) {
#pragma unroll
        for (int r = 0; r < 4; r++) {
            int i = tid + r * 256;
            int kq = i & 7, m = i >> 3;
            int gr = rowBase + m;
            float4 v = make_float4(0.f, 0.f, 0.f, 0.f);
            if (gr < M) v = *(const float4*)&A[(size_t)gr * FF + k0 + kq * 4];
            aSt[r] = v;
        }
#pragma unroll
        for (int r = 0; r < 2; r++) {
            int u = tid + r * 256;
            int kp = u >> 5, np = u & 31;
            const float* p0 = Bsrc + (size_t)(k0 + 2 * kp) * Bstride + colOff + 2 * np;
            bSt0[r] = *(const float2*)p0;
            bSt1[r] = *(const float2*)(p0 + Bstride);
        }
    };
    auto storeStage = [&](int buf) {
        uint32_t* Ah_ = sm + buf * BUF_SZ;
        uint32_t* Al_ = Ah_ + A_SZ;
        uint32_t* Bh_ = Al_ + A_SZ;
        uint32_t* Bl_ = Bh_ + B_SZ;
#pragma unroll
        for (int r = 0; r < 4; r++) {
            int i = tid + r * 256;
            int kq = i & 7, m = i >> 3;
            uint32_t hp0, lp0, hp1, lp1;
            splitpack(aSt[r].x, aSt[r].y, hp0, lp0);
            splitpack(aSt[r].z, aSt[r].w, hp1, lp1);
            *(uint2*)&Ah_[m * ARL + 2 * kq] = make_uint2(hp0, hp1);
            *(uint2*)&Al_[m * ARL + 2 * kq] = make_uint2(lp0, lp1);
        }
#pragma unroll
        for (int r = 0; r < 2; r++) {
            int u = tid + r * 256;
            int kp = u >> 5, np = u & 31;
            uint32_t hp0, lp0, hp1, lp1;
            splitpack(bSt0[r].x, bSt1[r].x, hp0, lp0);
            splitpack(bSt0[r].y, bSt1[r].y, hp1, lp1);
            *(uint2*)&Bh_[kp * BRL + 2 * np] = make_uint2(hp0, hp1);
            *(uint2*)&Bl_[kp * BRL + 2 * np] = make_uint2(lp0, lp1);
        }
    };

    float acc[2][4][4];
#pragma unroll
    for (int i = 0; i < 2; i++)
#pragma unroll
        for (int j = 0; j < 4; j++)
#pragma unroll
            for (int c = 0; c < 4; c++) acc[i][j][c] = 0.0f;

    const int nTiles = FF / BKT;
    loadStage(0);
    storeStage(0);
    __syncthreads();
    int buf = 0;
    for (int t = 0; t < nTiles; t++) {
        if (t + 1 < nTiles) loadStage((t + 1) * BKT);
        const uint32_t* Ah_ = sm + buf * BUF_SZ;
        const uint32_t* Al_ = Ah_ + A_SZ;
        const uint32_t* Bh_ = Al_ + A_SZ;
        const uint32_t* Bl_ = Bh_ + B_SZ;
#pragma unroll
        for (int kb = 0; kb < 2; kb++) {
            const int kb8 = kb * 8;
            uint32_t fah[2][4], fal[2][4], fbh[4][2], fbl[4][2];
#pragma unroll
            for (int i = 0; i < 2; i++) {
                int row = wm * 32 + i * 16 + lr;
                fah[i][0] = Ah_[row * ARL + kb8 + lc];
                fah[i][1] = Ah_[(row + 8) * ARL + kb8 + lc];
                fah[i][2] = Ah_[row * ARL + kb8 + lc + 4];
                fah[i][3] = Ah_[(row + 8) * ARL + kb8 + lc + 4];
                fal[i][0] = Al_[row * ARL + kb8 + lc];
                fal[i][1] = Al_[(row + 8) * ARL + kb8 + lc];
                fal[i][2] = Al_[row * ARL + kb8 + lc + 4];
                fal[i][3] = Al_[(row + 8) * ARL + kb8 + lc + 4];
            }
#pragma unroll
            for (int j = 0; j < 4; j++) {
                int n = wn * 32 + j * 8 + lr;
                fbh[j][0] = Bh_[(kb8 + lc) * BRL + n];
                fbh[j][1] = Bh_[(kb8 + lc + 4) * BRL + n];
                fbl[j][0] = Bl_[(kb8 + lc) * BRL + n];
                fbl[j][1] = Bl_[(kb8 + lc + 4) * BRL + n];
            }
#pragma unroll
            for (int i = 0; i < 2; i++)
#pragma unroll
                for (int j = 0; j < 4; j++) {
                    mma_bf16(acc[i][j], fah[i], fbh[j]);
                    mma_bf16(acc[i][j], fal[i], fbh[j]);
                    mma_bf16(acc[i][j], fah[i], fbl[j]);
                }
        }
        if (t + 1 < nTiles) storeStage(buf ^ 1);
        __syncthreads();
        buf ^= 1;
    }

#pragma unroll
    for (int i = 0; i < 2; i++) {
        int r0 = rowBase + wm * 32 + i * 16 + lr;
#pragma unroll
        for (int j = 0; j < 4; j++) {
            int gcl = wn * 32 + j * 8 + 2 * lc;
            if (!isXe) {
                int col = blockIdx.x * BNT + gcl;
                if (r0 < M)
                    *(float2*)&Cxw1[(size_t)r0 * HH + col] = make_float2(acc[i][j][0], acc[i][j][1]);
                if (r0 + 8 < M)
                    *(float2*)&Cxw1[(size_t)(r0 + 8) * HH + col] = make_float2(acc[i][j][2], acc[i][j][3]);
            } else {
                float b0 = __ldg(&bx[gcl]), b1 = __ldg(&bx[gcl + 1]);
                if (r0 < M)
                    *(float2*)&Cxe[(size_t)r0 * HXD + gcl] =
                        make_float2(fmaxf(acc[i][j][0] + b0, 0.f), fmaxf(acc[i][j][1] + b1, 0.f));
                if (r0 + 8 < M)
                    *(float2*)&Cxe[(size_t)(r0 + 8) * HXD + gcl] =
                        make_float2(fmaxf(acc[i][j][2] + b0, 0.f), fmaxf(acc[i][j][3] + b1, 0.f));
            }
        }
    }
}

// ---------------- fp32 GEMM for GEMM2 (relu on A; fused agg2 init in epilogue) ----------------
template <int BM, int BN, int BK, int TM, int TN, bool RELU_A, int MINB>
__global__ __launch_bounds__((BM / TM) * (BN / TN), MINB)
void sgemm_kernel(const float* __restrict__ A, const float* __restrict__ B,
                  float* __restrict__ C, int M, int N, int K,
                  const float* __restrict__ aggBias, float* __restrict__ aggOut) {
    constexpr int NT = (BM / TM) * (BN / TN);
    constexpr int AV = BM * BK / 4;
    constexpr int BV = BK * BN / 4;
    constexpr int AR = (AV + NT - 1) / NT;
    constexpr int BR = (BV + NT - 1) / NT;
    __shared__ float As[2][BK][BM];
    __shared__ float Bs[2][BK][BN];
    const int tid = threadIdx.x;
    const int tpr = BN / TN;
    const int tr = tid / tpr;
    const int tc = tid % tpr;
    const int rowBase = blockIdx.y * BM;
    const int colBase = blockIdx.x * BN;

    float4 aReg[AR], bReg[BR];

    auto loadTile = [&](int k0) {
#pragma unroll
        for (int r = 0; r < AR; r++) {
            int i = tid + r * NT;
            if ((AV % NT) && i >= AV) continue;
            int kq = i % (BK / 4);
            int m = i / (BK / 4);
            int gr = rowBase + m;
            float4 v = make_float4(0.f, 0.f, 0.f, 0.f);
            if (gr < M) v = *(const float4*)&A[(size_t)gr * K + k0 + kq * 4];
            if (RELU_A) {
                v.x = fmaxf(v.x, 0.f); v.y = fmaxf(v.y, 0.f);
                v.z = fmaxf(v.z, 0.f); v.w = fmaxf(v.w, 0.f);
            }
            aReg[r] = v;
        }
#pragma unroll
        for (int r = 0; r < BR; r++) {
            int i = tid + r * NT;
            if ((BV % NT) && i >= BV) continue;
            int nq = i % (BN / 4);
            int kk = i / (BN / 4);
            bReg[r] = *(const float4*)&B[(size_t)(k0 + kk) * N + colBase + nq * 4];
        }
    };
    auto storeTile = [&](int buf) {
#pragma unroll
        for (int r = 0; r < AR; r++) {
            int i = tid + r * NT;
            if ((AV % NT) && i >= AV) continue;
            int kq = i % (BK / 4);
            int m = i / (BK / 4);
            As[buf][kq * 4 + 0][m] = aReg[r].x;
            As[buf][kq * 4 + 1][m] = aReg[r].y;
            As[buf][kq * 4 + 2][m] = aReg[r].z;
            As[buf][kq * 4 + 3][m] = aReg[r].w;
        }
#pragma unroll
        for (int r = 0; r < BR; r++) {
            int i = tid + r * NT;
            if ((BV % NT) && i >= BV) continue;
            int nq = i % (BN / 4);
            int kk = i / (BN / 4);
            *(float4*)&Bs[buf][kk][nq * 4] = bReg[r];
        }
    };

    float acc[TM][TN];
#pragma unroll
    for (int i = 0; i < TM; i++)
#pragma unroll
        for (int j = 0; j < TN; j++) acc[i][j] = 0.0f;

    const int nTiles = K / BK;
    loadTile(0);
    storeTile(0);
    __syncthreads();
    int buf = 0;
    for (int t = 0; t < nTiles; t++) {
        if (t + 1 < nTiles) loadTile((t + 1) * BK);
#pragma unroll
        for (int kk = 0; kk < BK; kk++) {
            float ra[TM], rb[TN];
#pragma unroll
            for (int i = 0; i < TM; i++) ra[i] = As[buf][kk][tr * TM + i];
#pragma unroll
            for (int j = 0; j < TN; j++) rb[j] = Bs[buf][kk][tc * TN + j];
#pragma unroll
            for (int i = 0; i < TM; i++)
#pragma unroll
                for (int j = 0; j < TN; j++) acc[i][j] += ra[i] * rb[j];
        }
        if (t + 1 < nTiles) storeTile(buf ^ 1);
        __syncthreads();
        buf ^= 1;
    }

#pragma unroll
    for (int i = 0; i < TM; i++) {
        int gr = rowBase + tr * TM + i;
        if (gr >= M) continue;
        float dsc = aggOut ? (1.0f / (float)(g_cnt[gr] + 1)) : 0.0f;
#pragma unroll
        for (int j = 0; j < TN; j++) {
            int gc = colBase + tc * TN + j;
            float val = acc[i][j];
            C[(size_t)gr * N + gc] = val;
            if (aggOut)
                aggOut[(size_t)gr * N + gc] = dsc * val + __ldg(&aggBias[gc]);
        }
    }
}

// ---------------- init agg1 = dinv^2 * xw1 + b1 (self loop + bias) ----------------
__global__ void init_agg1_kernel(const float* __restrict__ b1) {
    int i = blockIdx.x * blockDim.x + threadIdx.x;     // float4 index
    if (i >= NN * (HH / 4)) return;
    int n = i / (HH / 4);
    int q = i % (HH / 4);
    float sc = 1.0f / (float)(g_cnt[n] + 1);
    float4 xv = ((const float4*)g_xw1)[i];
    float4 bv = __ldg(&((const float4*)b1)[q]);
    float4 o;
    o.x = sc * xv.x + bv.x; o.y = sc * xv.y + bv.y;
    o.z = sc * xv.z + bv.z; o.w = sc * xv.w + bv.w;
    ((float4*)g_agg1)[i] = o;
}

// ---------------- layer-1 segmented scatter: warp per 4 dst-sorted edges ----------------
__global__ void scatter1_seg_kernel() {
    int w = (blockIdx.x * blockDim.x + threadIdx.x) >> 5;
    int lane = threadIdx.x & 31;
    int e0 = w * 4;
    if (e0 >= EE) return;
    int e1 = e0 + 4; if (e1 > EE) e1 = EE;
    float4 acc = make_float4(0.f, 0.f, 0.f, 0.f);
    int cur = -1;
    for (int e = e0; e < e1; e++) {
        int d = __ldg(&g_csrd[e]);             // warp-uniform
        if (d != cur) {
            if (cur >= 0) {
                float* p = &g_agg1[(size_t)cur * HH + lane * 4];
                asm volatile("red.global.add.v4.f32 [%0], {%1,%2,%3,%4};"
                             :: "l"(p), "f"(acc.x), "f"(acc.y), "f"(acc.z), "f"(acc.w)
                             : "memory");
                acc = make_float4(0.f, 0.f, 0.f, 0.f);
            }
            cur = d;
        }
        int2 sn = __ldg(&g_csr[e]);
        float nm = __int_as_float(sn.y);
        float4 v = *(const float4*)&g_xw1[(size_t)sn.x * HH + lane * 4];
        acc.x += nm * v.x; acc.y += nm * v.y;
        acc.z += nm * v.z; acc.w += nm * v.w;
    }
    if (cur >= 0) {
        float* p = &g_agg1[(size_t)cur * HH + lane * 4];
        asm volatile("red.global.add.v4.f32 [%0], {%1,%2,%3,%4};"
                     :: "l"(p), "f"(acc.x), "f"(acc.y), "f"(acc.z), "f"(acc.w)
                     : "memory");
    }
}

// ---------------- layer-2 segmented scatter: 4 threads per 4 dst-sorted edges ----------------
__global__ void scatter2_seg_kernel() {
    int gt = blockIdx.x * blockDim.x + threadIdx.x;
    int g = gt >> 2, q = gt & 3;
    int e0 = g * 4;
    if (e0 >= EE) return;
    int e1 = e0 + 4; if (e1 > EE) e1 = EE;
    float4 acc = make_float4(0.f, 0.f, 0.f, 0.f);
    int cur = -1;
    for (int e = e0; e < e1; e++) {
        int d = __ldg(&g_csrd[e]);
        if (d != cur) {
            if (cur >= 0) {
                float* p = &g_agg2[(size_t)cur * CC + q * 4];
                asm volatile("red.global.add.v4.f32 [%0], {%1,%2,%3,%4};"
                             :: "l"(p), "f"(acc.x), "f"(acc.y), "f"(acc.z), "f"(acc.w)
                             : "memory");
                acc = make_float4(0.f, 0.f, 0.f, 0.f);
            }
            cur = d;
        }
        int2 sn = __ldg(&g_csr[e]);
        float nm = __int_as_float(sn.y);
        float4 v = ((const float4*)&g_xw2[(size_t)sn.x * CC])[q];
        acc.x += nm * v.x; acc.y += nm * v.y;
        acc.z += nm * v.z; acc.w += nm * v.w;
    }
    if (cur >= 0) {
        float* p = &g_agg2[(size_t)cur * CC + q * 4];
        asm volatile("red.global.add.v4.f32 [%0], {%1,%2,%3,%4};"
                     :: "l"(p), "f"(acc.x), "f"(acc.y), "f"(acc.z), "f"(acc.w)
                     : "memory");
    }
}

// ---------------- per-node: log_softmax, y_prob, u/v scalars ----------------
__global__ void node_kernel(const int* __restrict__ y, const void* __restrict__ tmask,
                            const float* __restrict__ Wd, float* __restrict__ out_lsm) {
    int n = blockIdx.x * blockDim.x + threadIdx.x;
    if (n >= NN) return;
    float l[CC];
    const float* lr = &g_agg2[(size_t)n * CC];
    float m = -1e30f;
#pragma unroll
    for (int c = 0; c < CC; c++) { l[c] = lr[c]; m = fmaxf(m, l[c]); }
    float se = 0.0f;
#pragma unroll
    for (int c = 0; c < CC; c++) se += expf(l[c] - m);
    float lse = logf(se);

    int kind = g_maskkind;
    bool msk;
    if (kind == 0)      msk = ((const int*)tmask)[n] != 0;
    else if (kind == 1) msk = ((const float*)tmask)[n] != 0.0f;
    else                msk = ((const unsigned char*)tmask)[n] != 0;
    int yc = y[n];

    float u = 0.0f, v = 0.0f;
#pragma unroll
    for (int c = 0; c < CC; c++) {
        float lsm = l[c] - m - lse;
        out_lsm[(size_t)n * CC + c] = lsm;
        float yp = msk ? ((c == yc) ? 1.0f : 0.0f) : expf(lsm);
        u += yp * __ldg(&Wd[128 + c]);
        v += yp * __ldg(&Wd[144 + c]);
    }
    const float4* xr = (const float4*)&g_xe[(size_t)n * HXD];
#pragma unroll
    for (int k4 = 0; k4 < HXD / 4; k4++) {
        float4 xv = xr[k4];
        int k = k4 * 4;
        u += xv.x * __ldg(&Wd[k + 0]) + xv.y * __ldg(&Wd[k + 1])
           + xv.z * __ldg(&Wd[k + 2]) + xv.w * __ldg(&Wd[k + 3]);
        v += xv.x * __ldg(&Wd[64 + k + 0]) + xv.y * __ldg(&Wd[64 + k + 1])
           + xv.z * __ldg(&Wd[64 + k + 2]) + xv.w * __ldg(&Wd[64 + k + 3]);
    }
    g_u[n] = u;
    g_v[n] = v;
}

// ---------------- edge decode ----------------
__global__ void decode_kernel(const int* __restrict__ pos, const int* __restrict__ neg,
                              const float* __restrict__ bd, float* __restrict__ out) {
    int i = blockIdx.x * blockDim.x + threadIdx.x;
    if (i >= 2 * EE) return;
    const int* ei = (i < EE) ? pos : neg;
    int k = (i < EE) ? i : i - EE;
    int s = ei[k];
    int d = ei[EE + k];
    out[i] = g_u[s] + g_v[d] + __ldg(bd);
}

// ---------------- launch ----------------
extern "C" void kernel_launch(void* const* d_in, const int* in_sizes, int n_in,
                              void* d_out, int out_size) {
    const float* x  = (const float*)d_in[0];
    const int* ei   = (const int*)d_in[1];   // [2, E] row-major: src then dst
    const int* nei  = (const int*)d_in[2];
    const int* y    = (const int*)d_in[3];
    const void* tm  = d_in[4];
    const float* W1 = (const float*)d_in[5];
    const float* b1 = (const float*)d_in[6];
    const float* W2 = (const float*)d_in[7];
    const float* b2 = (const float*)d_in[8];
    const float* Wx = (const float*)d_in[9];
    const float* bx = (const float*)d_in[10];
    const float* Wd = (const float*)d_in[11];
    const float* bd = (const float*)d_in[12];
    float* out = (float*)d_out;

    float *p_xw1, *p_xe, *p_agg1, *p_xw2, *p_agg2;
    cudaGetSymbolAddress((void**)&p_xw1, g_xw1);
    cudaGetSymbolAddress((void**)&p_xe, g_xe);
    cudaGetSymbolAddress((void**)&p_agg1, g_agg1);
    cudaGetSymbolAddress((void**)&p_xw2, g_xw2);
    cudaGetSymbolAddress((void**)&p_agg2, g_agg2);

    static cudaStream_t s1 = nullptr;
    static cudaEvent_t evFork = nullptr, evJoin = nullptr;
    if (!s1) {
        cudaStreamCreateWithFlags(&s1, cudaStreamNonBlocking);
        cudaEventCreateWithFlags(&evFork, cudaEventDisableTiming);
        cudaEventCreateWithFlags(&evJoin, cudaEventDisableTiming);
        cudaFuncSetAttribute(bf16_fused_gemm_kernel,
                             cudaFuncAttributeMaxDynamicSharedMemorySize, SMEM_BYTES);
    }

    const int T = 256;

    prep_kernel<<<(NN + T - 1) / T, T>>>((const unsigned*)tm);
    cudaEventRecord(evFork, 0);
    cudaStreamWaitEvent(s1, evFork, 0);

    // side stream: CSR build (dst-sorted edges), hidden under the fused GEMM
    deg_count_kernel<<<(EE + T - 1) / T, T, 0, s1>>>(ei + EE);
    csr_scan_kernel<<<1, 1024, 0, s1>>>();
    csr_fill_kernel<<<(EE + T - 1) / T, T, 0, s1>>>(ei, ei + EE);
    cudaEventRecord(evJoin, s1);

    {   // fused tensor-core GEMM: [xw1 | xe] = x @ [W1 | Wx]  (3xBF16, R8 config)
        dim3 grid(3, (NN + BMT - 1) / BMT);
        bf16_fused_gemm_kernel<<<grid, 256, SMEM_BYTES>>>(x, W1, Wx, bx, p_xw1, p_xe, NN);
    }
    cudaStreamWaitEvent(0, evJoin, 0);

    init_agg1_kernel<<<(NN * (HH / 4) + T - 1) / T, T>>>(b1);
    {   // layer-1 segmented scatter: warp per 4 sorted edges
        int warps = (EE + 3) / 4;
        int blocks = (warps * 32 + T - 1) / T;
        scatter1_seg_kernel<<<blocks, T>>>();
    }

    {   // xw2 = relu(agg1) @ W2 with fused agg2-init epilogue (self loop + b2)
        dim3 grid(CC / 16, (NN + 127) / 128);
        sgemm_kernel<128, 16, 16, 8, 2, true, 2><<<grid, 128>>>(
            p_agg1, W2, p_xw2, NN, CC, HH, b2, p_agg2);
    }
    {   // layer-2 segmented scatter: 4 threads per 4 sorted edges
        int groups = (EE + 3) / 4;
        int blocks = (groups * 4 + T - 1) / T;
        scatter2_seg_kernel<<<blocks, T>>>();
    }

    node_kernel<<<(NN + T - 1) / T, T>>>(y, tm, Wd, out + 2 * (size_t)EE);
    decode_kernel<<<(2 * EE + T - 1) / T, T>>>(ei, nei, bd, out);
}

// round 16
// speedup vs baseline: 1.3236x; 1.3236x over previous
#include <cuda_runtime.h>
#include <math.h>
#include <stdint.h>

#define NN  50000
#define FF  256
#define HH  128
#define CC  16
#define HXD 64
#define EE  500000

// ---------------- scratch (device globals; no allocation allowed) ----------------
__device__ float g_xw1 [(size_t)NN * HH];   // x @ W1
__device__ float g_xe  [(size_t)NN * HXD];  // relu(x @ Wx + bx)
__device__ float g_agg1[(size_t)NN * HH];   // layer-1 aggregate (relu fused into GEMM2 load)
__device__ float g_xw2 [(size_t)NN * CC];   // h @ W2
__device__ float g_agg2[(size_t)NN * CC];   // layer-2 aggregate = logits
__device__ float g_deg [NN];
__device__ float g_norm[EE];
__device__ float g_u   [NN];
__device__ float g_v   [NN];
__device__ int   g_maskkind;                // 0=int32, 1=float32, 2=byte/bool

// ---------------- prep: deg=1 (self loop) + train_mask dtype detection ----------------
__global__ void prep_kernel(const unsigned* __restrict__ tm) {
    int i = blockIdx.x * blockDim.x + threadIdx.x;
    if (i < NN) g_deg[i] = 1.0f;
    if (blockIdx.x == 0) {
        __shared__ int bad_int, bad_float;
        if (threadIdx.x == 0) { bad_int = 0; bad_float = 0; }
        __syncthreads();
        for (int j = threadIdx.x; j < 2048; j += blockDim.x) {
            unsigned v = tm[j];
            if (v > 1u) bad_int = 1;                          // benign write race
            if (v != 0u && v != 0x3F800000u) bad_float = 1;
        }
        __syncthreads();
        if (threadIdx.x == 0)
            g_maskkind = (bad_int == 0) ? 0 : ((bad_float == 0) ? 1 : 2);
    }
}

__global__ void deg_count_kernel(const int* __restrict__ dst) {
    int e = blockIdx.x * blockDim.x + threadIdx.x;
    if (e < EE) atomicAdd(&g_deg[dst[e]], 1.0f);
}

__global__ void norm_kernel(const int* __restrict__ src, const int* __restrict__ dst) {
    int e = blockIdx.x * blockDim.x + threadIdx.x;
    if (e < EE) g_norm[e] = rsqrtf(g_deg[src[e]]) * rsqrtf(g_deg[dst[e]]);
}

// ================= fused 3xBF16 tensor-core GEMM (R8 config) =================
// xePart=0: grid.x in {0,1} -> xw1 columns.  xePart=1: this launch computes xe.
#define BMT 128
#define BNT 64
#define BKT 32
#define ARL 20
#define BRL 72
#define A_SZ (BMT * ARL)
#define B_SZ ((BKT / 2) * BRL)
#define BUF_SZ (2 * A_SZ + 2 * B_SZ)
#define SMEM_BYTES (2 * BUF_SZ * 4)

__device__ __forceinline__ void splitpack(float e, float o, uint32_t& hp, uint32_t& lp) {
    asm("cvt.rn.bf16x2.f32 %0, %1, %2;" : "=r"(hp) : "f"(o), "f"(e));
    float he = __uint_as_float(hp << 16);
    float ho = __uint_as_float(hp & 0xFFFF0000u);
    float le = e - he, lo = o - ho;
    asm("cvt.rn.bf16x2.f32 %0, %1, %2;" : "=r"(lp) : "f"(lo), "f"(le));
}

__device__ __forceinline__ void mma_bf16(float* c, const uint32_t* a, const uint32_t* b) {
    asm volatile(
        "mma.sync.aligned.m16n8k16.row.col.f32.bf16.bf16.f32 "
        "{%0,%1,%2,%3}, {%4,%5,%6,%7}, {%8,%9}, {%0,%1,%2,%3};"
        : "+f"(c[0]), "+f"(c[1]), "+f"(c[2]), "+f"(c[3])
        : "r"(a[0]), "r"(a[1]), "r"(a[2]), "r"(a[3]), "r"(b[0]), "r"(b[1]));
}

__global__ __launch_bounds__(256, 2)
void bf16_fused_gemm_kernel(const float* __restrict__ A,
                            const float* __restrict__ W1,
                            const float* __restrict__ Wx,
                            const float* __restrict__ bx,
                            float* __restrict__ Cxw1,
                            float* __restrict__ Cxe,
                            int M, int xePart) {
    extern __shared__ uint32_t sm[];

    const int tid = threadIdx.x;
    const int rowBase = blockIdx.y * BMT;
    const bool isXe = (xePart != 0);
    const float* Bsrc = isXe ? Wx : W1;
    const int Bstride = isXe ? HXD : HH;
    const int colOff = isXe ? 0 : blockIdx.x * BNT;

    const int warp = tid >> 5, lane = tid & 31;
    const int wm = warp >> 1, wn = warp & 1;
    const int lr = lane >> 2, lc = lane & 3;

    float4 aSt[4];
    float2 bSt0[2], bSt1[2];

    auto loadStage = [&](int k0) {
#pragma unroll
        for (int r = 0; r < 4; r++) {
            int i = tid + r * 256;
            int kq = i & 7, m = i >> 3;
            int gr = rowBase + m;
            float4 v = make_float4(0.f, 0.f, 0.f, 0.f);
            if (gr < M) v = *(const float4*)&A[(size_t)gr * FF + k0 + kq * 4];
            aSt[r] = v;
        }
#pragma unroll
        for (int r = 0; r < 2; r++) {
            int u = tid + r * 256;
            int kp = u >> 5, np = u & 31;
            const float* p0 = Bsrc + (size_t)(k0 + 2 * kp) * Bstride + colOff + 2 * np;
            bSt0[r] = *(const float2*)p0;
            bSt1[r] = *(const float2*)(p0 + Bstride);
        }
    };
    auto storeStage = [&](int buf) {
        uint32_t* Ah_ = sm + buf * BUF_SZ;
        uint32_t* Al_ = Ah_ + A_SZ;
        uint32_t* Bh_ = Al_ + A_SZ;
        uint32_t* Bl_ = Bh_ + B_SZ;
#pragma unroll
        for (int r = 0; r < 4; r++) {
            int i = tid + r * 256;
            int kq = i & 7, m = i >> 3;
            uint32_t hp0, lp0, hp1, lp1;
            splitpack(aSt[r].x, aSt[r].y, hp0, lp0);
            splitpack(aSt[r].z, aSt[r].w, hp1, lp1);
            *(uint2*)&Ah_[m * ARL + 2 * kq] = make_uint2(hp0, hp1);
            *(uint2*)&Al_[m * ARL + 2 * kq] = make_uint2(lp0, lp1);
        }
#pragma unroll
        for (int r = 0; r < 2; r++) {
            int u = tid + r * 256;
            int kp = u >> 5, np = u & 31;
            uint32_t hp0, lp0, hp1, lp1;
            splitpack(bSt0[r].x, bSt1[r].x, hp0, lp0);
            splitpack(bSt0[r].y, bSt1[r].y, hp1, lp1);
            *(uint2*)&Bh_[kp * BRL + 2 * np] = make_uint2(hp0, hp1);
            *(uint2*)&Bl_[kp * BRL + 2 * np] = make_uint2(lp0, lp1);
        }
    };

    float acc[2][4][4];
#pragma unroll
    for (int i = 0; i < 2; i++)
#pragma unroll
        for (int j = 0; j < 4; j++)
#pragma unroll
            for (int c = 0; c < 4; c++) acc[i][j][c] = 0.0f;

    const int nTiles = FF / BKT;
    loadStage(0);
    storeStage(0);
    __syncthreads();
    int buf = 0;
    for (int t = 0; t < nTiles; t++) {
        if (t + 1 < nTiles) loadStage((t + 1) * BKT);
        const uint32_t* Ah_ = sm + buf * BUF_SZ;
        const uint32_t* Al_ = Ah_ + A_SZ;
        const uint32_t* Bh_ = Al_ + A_SZ;
        const uint32_t* Bl_ = Bh_ + B_SZ;
#pragma unroll
        for (int kb = 0; kb < 2; kb++) {
            const int kb8 = kb * 8;
            uint32_t fah[2][4], fal[2][4], fbh[4][2], fbl[4][2];
#pragma unroll
            for (int i = 0; i < 2; i++) {
                int row = wm * 32 + i * 16 + lr;
                fah[i][0] = Ah_[row * ARL + kb8 + lc];
                fah[i][1] = Ah_[(row + 8) * ARL + kb8 + lc];
                fah[i][2] = Ah_[row * ARL + kb8 + lc + 4];
                fah[i][3] = Ah_[(row + 8) * ARL + kb8 + lc + 4];
                fal[i][0] = Al_[row * ARL + kb8 + lc];
                fal[i][1] = Al_[(row + 8) * ARL + kb8 + lc];
                fal[i][2] = Al_[row * ARL + kb8 + lc + 4];
                fal[i][3] = Al_[(row + 8) * ARL + kb8 + lc + 4];
            }
#pragma unroll
            for (int j = 0; j < 4; j++) {
                int n = wn * 32 + j * 8 + lr;
                fbh[j][0] = Bh_[(kb8 + lc) * BRL + n];
                fbh[j][1] = Bh_[(kb8 + lc + 4) * BRL + n];
                fbl[j][0] = Bl_[(kb8 + lc) * BRL + n];
                fbl[j][1] = Bl_[(kb8 + lc + 4) * BRL + n];
            }
#pragma unroll
            for (int i = 0; i < 2; i++)
#pragma unroll
                for (int j = 0; j < 4; j++) {
                    mma_bf16(acc[i][j], fah[i], fbh[j]);
                    mma_bf16(acc[i][j], fal[i], fbh[j]);
                    mma_bf16(acc[i][j], fah[i], fbl[j]);
                }
        }
        if (t + 1 < nTiles) storeStage(buf ^ 1);
        __syncthreads();
        buf ^= 1;
    }

#pragma unroll
    for (int i = 0; i < 2; i++) {
        int r0 = rowBase + wm * 32 + i * 16 + lr;
#pragma unroll
        for (int j = 0; j < 4; j++) {
            int gcl = wn * 32 + j * 8 + 2 * lc;
            if (!isXe) {
                int col = blockIdx.x * BNT + gcl;
                if (r0 < M)
                    *(float2*)&Cxw1[(size_t)r0 * HH + col] = make_float2(acc[i][j][0], acc[i][j][1]);
                if (r0 + 8 < M)
                    *(float2*)&Cxw1[(size_t)(r0 + 8) * HH + col] = make_float2(acc[i][j][2], acc[i][j][3]);
            } else {
                float b0 = __ldg(&bx[gcl]), b1 = __ldg(&bx[gcl + 1]);
                if (r0 < M)
                    *(float2*)&Cxe[(size_t)r0 * HXD + gcl] =
                        make_float2(fmaxf(acc[i][j][0] + b0, 0.f), fmaxf(acc[i][j][1] + b1, 0.f));
                if (r0 + 8 < M)
                    *(float2*)&Cxe[(size_t)(r0 + 8) * HXD + gcl] =
                        make_float2(fmaxf(acc[i][j][2] + b0, 0.f), fmaxf(acc[i][j][3] + b1, 0.f));
            }
        }
    }
}

// ---------------- double-buffered (smem only) fp32 GEMM (used for GEMM2) ----------------
template <int BM, int BN, int BK, int TM, int TN, bool RELU_A, int MINB>
__global__ __launch_bounds__((BM / TM) * (BN / TN), MINB)
void sgemm_kernel(const float* __restrict__ A, const float* __restrict__ B,
                  const float* __restrict__ bias, float* __restrict__ C,
                  int M, int N, int K, int doRelu) {
    constexpr int NT = (BM / TM) * (BN / TN);
    constexpr int AV = BM * BK / 4;
    constexpr int BV = BK * BN / 4;
    constexpr int AR = (AV + NT - 1) / NT;
    constexpr int BR = (BV + NT - 1) / NT;
    __shared__ float As[2][BK][BM];
    __shared__ float Bs[2][BK][BN];
    const int tid = threadIdx.x;
    const int tpr = BN / TN;
    const int tr = tid / tpr;
    const int tc = tid % tpr;
    const int rowBase = blockIdx.y * BM;
    const int colBase = blockIdx.x * BN;

    float4 aReg[AR], bReg[BR];

    auto loadTile = [&](int k0) {
#pragma unroll
        for (int r = 0; r < AR; r++) {
            int i = tid + r * NT;
            if ((AV % NT) && i >= AV) continue;
            int kq = i % (BK / 4);
            int m = i / (BK / 4);
            int gr = rowBase + m;
            float4 v = make_float4(0.f, 0.f, 0.f, 0.f);
            if (gr < M) v = *(const float4*)&A[(size_t)gr * K + k0 + kq * 4];
            if (RELU_A) {
                v.x = fmaxf(v.x, 0.f); v.y = fmaxf(v.y, 0.f);
                v.z = fmaxf(v.z, 0.f); v.w = fmaxf(v.w, 0.f);
            }
            aReg[r] = v;
        }
#pragma unroll
        for (int r = 0; r < BR; r++) {
            int i = tid + r * NT;
            if ((BV % NT) && i >= BV) continue;
            int nq = i % (BN / 4);
            int kk = i / (BN / 4);
            bReg[r] = *(const float4*)&B[(size_t)(k0 + kk) * N + colBase + nq * 4];
        }
    };
    auto storeTile = [&](int buf) {
#pragma unroll
        for (int r = 0; r < AR; r++) {
            int i = tid + r * NT;
            if ((AV % NT) && i >= AV) continue;
            int kq = i % (BK / 4);
            int m = i / (BK / 4);
            As[buf][kq * 4 + 0][m] = aReg[r].x;
            As[buf][kq * 4 + 1][m] = aReg[r].y;
            As[buf][kq * 4 + 2][m] = aReg[r].z;
            As[buf][kq * 4 + 3][m] = aReg[r].w;
        }
#pragma unroll
        for (int r = 0; r < BR; r++) {
            int i = tid + r * NT;
            if ((BV % NT) && i >= BV) continue;
            int nq = i % (BN / 4);
            int kk = i / (BN / 4);
            *(float4*)&Bs[buf][kk][nq * 4] = bReg[r];
        }
    };

    float acc[TM][TN];
#pragma unroll
    for (int i = 0; i < TM; i++)
#pragma unroll
        for (int j = 0; j < TN; j++) acc[i][j] = 0.0f;

    const int nTiles = K / BK;
    loadTile(0);
    storeTile(0);
    __syncthreads();
    int buf = 0;
    for (int t = 0; t < nTiles; t++) {
        if (t + 1 < nTiles) loadTile((t + 1) * BK);
#pragma unroll
        for (int kk = 0; kk < BK; kk++) {
            float ra[TM], rb[TN];
#pragma unroll
            for (int i = 0; i < TM; i++) ra[i] = As[buf][kk][tr * TM + i];
#pragma unroll
            for (int j = 0; j < TN; j++) rb[j] = Bs[buf][kk][tc * TN + j];
#pragma unroll
            for (int i = 0; i < TM; i++)
#pragma unroll
                for (int j = 0; j < TN; j++) acc[i][j] += ra[i] * rb[j];
        }
        if (t + 1 < nTiles) storeTile(buf ^ 1);
        __syncthreads();
        buf ^= 1;
    }

#pragma unroll
    for (int i = 0; i < TM; i++) {
        int gr = rowBase + tr * TM + i;
        if (gr >= M) continue;
#pragma unroll
        for (int j = 0; j < TN; j++) {
            int gc = colBase + tc * TN + j;
            float val = acc[i][j] + (bias ? bias[gc] : 0.0f);
            if (doRelu) val = fmaxf(val, 0.0f);
            C[(size_t)gr * N + gc] = val;
        }
    }
}

// ---------------- layer-1 aggregation (RED-based, R8 structure) ----------------
__global__ void init_agg1_kernel(const float* __restrict__ b1) {
    int i = blockIdx.x * blockDim.x + threadIdx.x;     // float4 index
    if (i >= NN * (HH / 4)) return;
    int n = i / (HH / 4);
    int q = i % (HH / 4);
    float di = rsqrtf(g_deg[n]);
    float sc = di * di;
    float4 xv = ((const float4*)g_xw1)[i];
    float4 bv = __ldg(&((const float4*)b1)[q]);
    float4 o;
    o.x = sc * xv.x + bv.x; o.y = sc * xv.y + bv.y;
    o.z = sc * xv.z + bv.z; o.w = sc * xv.w + bv.w;
    ((float4*)g_agg1)[i] = o;
}

__global__ void scatter1_kernel(const int* __restrict__ src, const int* __restrict__ dst) {
    const int EPW = 4;  // edges per warp
    int w = (blockIdx.x * blockDim.x + threadIdx.x) >> 5;
    int lane = threadIdx.x & 31;
    int e0 = w * EPW;
    int e1 = e0 + EPW; if (e1 > EE) e1 = EE;
    for (int e = e0; e < e1; e++) {
        int s = __ldg(&src[e]);
        int d = __ldg(&dst[e]);
        float nm = g_norm[e];
        float4 v = *(const float4*)&g_xw1[(size_t)s * HH + lane * 4];
        float* p = &g_agg1[(size_t)d * HH + lane * 4];
        asm volatile("red.global.add.v4.f32 [%0], {%1,%2,%3,%4};"
                     :: "l"(p), "f"(nm * v.x), "f"(nm * v.y), "f"(nm * v.z), "f"(nm * v.w)
                     : "memory");
    }
}

// ---------------- layer-2 aggregation ----------------
__global__ void init_agg2_kernel(const float* __restrict__ b2) {
    int i = blockIdx.x * blockDim.x + threadIdx.x;     // float4 index
    if (i >= NN * (CC / 4)) return;
    int n = i / (CC / 4);
    int q = i % (CC / 4);
    float di = rsqrtf(g_deg[n]);
    float sc = di * di;
    float4 xv = ((const float4*)g_xw2)[i];
    float4 bv = __ldg(&((const float4*)b2)[q]);
    float4 o;
    o.x = sc * xv.x + bv.x; o.y = sc * xv.y + bv.y;
    o.z = sc * xv.z + bv.z; o.w = sc * xv.w + bv.w;
    ((float4*)g_agg2)[i] = o;
}

__global__ void scatter2_kernel(const int* __restrict__ src, const int* __restrict__ dst) {
    int gt = blockIdx.x * blockDim.x + threadIdx.x;
    int e = gt >> 2;          // 4 threads per edge (16 floats)
    int q = gt & 3;
    if (e >= EE) return;
    int s = __ldg(&src[e]);
    int d = __ldg(&dst[e]);
    float nm = g_norm[e];
    float4 v = ((const float4*)&g_xw2[(size_t)s * CC])[q];
    float* p = &g_agg2[(size_t)d * CC + q * 4];
    asm volatile("red.global.add.v4.f32 [%0], {%1,%2,%3,%4};"
                 :: "l"(p), "f"(nm * v.x), "f"(nm * v.y), "f"(nm * v.z), "f"(nm * v.w)
                 : "memory");
}

// ---------------- per-node: log_softmax, y_prob, u/v scalars ----------------
__global__ void node_kernel(const int* __restrict__ y, const void* __restrict__ tmask,
                            const float* __restrict__ Wd, float* __restrict__ out_lsm) {
    int n = blockIdx.x * blockDim.x + threadIdx.x;
    if (n >= NN) return;
    float l[CC];
    const float* lr = &g_agg2[(size_t)n * CC];
    float m = -1e30f;
#pragma unroll
    for (int c = 0; c < CC; c++) { l[c] = lr[c]; m = fmaxf(m, l[c]); }
    float se = 0.0f;
#pragma unroll
    for (int c = 0; c < CC; c++) se += expf(l[c] - m);
    float lse = logf(se);

    int kind = g_maskkind;
    bool msk;
    if (kind == 0)      msk = ((const int*)tmask)[n] != 0;
    else if (kind == 1) msk = ((const float*)tmask)[n] != 0.0f;
    else                msk = ((const unsigned char*)tmask)[n] != 0;
    int yc = y[n];

    float u = 0.0f, v = 0.0f;
#pragma unroll
    for (int c = 0; c < CC; c++) {
        float lsm = l[c] - m - lse;
        out_lsm[(size_t)n * CC + c] = lsm;
        float yp = msk ? ((c == yc) ? 1.0f : 0.0f) : expf(lsm);
        u += yp * __ldg(&Wd[128 + c]);
        v += yp * __ldg(&Wd[144 + c]);
    }
    const float4* xr = (const float4*)&g_xe[(size_t)n * HXD];
#pragma unroll
    for (int k4 = 0; k4 < HXD / 4; k4++) {
        float4 xv = xr[k4];
        int k = k4 * 4;
        u += xv.x * __ldg(&Wd[k + 0]) + xv.y * __ldg(&Wd[k + 1])
           + xv.z * __ldg(&Wd[k + 2]) + xv.w * __ldg(&Wd[k + 3]);
        v += xv.x * __ldg(&Wd[64 + k + 0]) + xv.y * __ldg(&Wd[64 + k + 1])
           + xv.z * __ldg(&Wd[64 + k + 2]) + xv.w * __ldg(&Wd[64 + k + 3]);
    }
    g_u[n] = u;
    g_v[n] = v;
}

// ---------------- edge decode ----------------
__global__ void decode_kernel(const int* __restrict__ pos, const int* __restrict__ neg,
                              const float* __restrict__ bd, float* __restrict__ out) {
    int i = blockIdx.x * blockDim.x + threadIdx.x;
    if (i >= 2 * EE) return;
    const int* ei = (i < EE) ? pos : neg;
    int k = (i < EE) ? i : i - EE;
    int s = ei[k];
    int d = ei[EE + k];
    out[i] = g_u[s] + g_v[d] + __ldg(bd);
}

// ---------------- launch ----------------
extern "C" void kernel_launch(void* const* d_in, const int* in_sizes, int n_in,
                              void* d_out, int out_size) {
    const float* x  = (const float*)d_in[0];
    const int* ei   = (const int*)d_in[1];   // [2, E] row-major: src then dst
    const int* nei  = (const int*)d_in[2];
    const int* y    = (const int*)d_in[3];
    const void* tm  = d_in[4];
    const float* W1 = (const float*)d_in[5];
    const float* b1 = (const float*)d_in[6];
    const float* W2 = (const float*)d_in[7];
    const float* b2 = (const float*)d_in[8];
    const float* Wx = (const float*)d_in[9];
    const float* bx = (const float*)d_in[10];
    const float* Wd = (const float*)d_in[11];
    const float* bd = (const float*)d_in[12];
    float* out = (float*)d_out;

    float *p_xw1, *p_xe, *p_agg1, *p_xw2;
    cudaGetSymbolAddress((void**)&p_xw1, g_xw1);
    cudaGetSymbolAddress((void**)&p_xe, g_xe);
    cudaGetSymbolAddress((void**)&p_agg1, g_agg1);
    cudaGetSymbolAddress((void**)&p_xw2, g_xw2);

    static cudaStream_t s1 = nullptr;
    static cudaEvent_t evFork = nullptr, evDeg = nullptr, evXe = nullptr;
    if (!s1) {
        cudaStreamCreateWithFlags(&s1, cudaStreamNonBlocking);
        cudaEventCreateWithFlags(&evFork, cudaEventDisableTiming);
        cudaEventCreateWithFlags(&evDeg, cudaEventDisableTiming);
        cudaEventCreateWithFlags(&evXe, cudaEventDisableTiming);
        cudaFuncSetAttribute(bf16_fused_gemm_kernel,
                             cudaFuncAttributeMaxDynamicSharedMemorySize, SMEM_BYTES);
    }

    const int T = 256;

    prep_kernel<<<(NN + T - 1) / T, T>>>((const unsigned*)tm);
    cudaEventRecord(evFork, 0);
    cudaStreamWaitEvent(s1, evFork, 0);

    // side stream: degree + norm, then the xe-GEMM third (only needed by node_kernel)
    deg_count_kernel<<<(EE + T - 1) / T, T, 0, s1>>>(ei + EE);
    norm_kernel<<<(EE + T - 1) / T, T, 0, s1>>>(ei, ei + EE);
    cudaEventRecord(evDeg, s1);
    {   // xe = relu(x @ Wx + bx)  (overlaps main-stream scatter chain)
        dim3 grid(1, (NN + BMT - 1) / BMT);
        bf16_fused_gemm_kernel<<<grid, 256, SMEM_BYTES, s1>>>(x, W1, Wx, bx, p_xw1, p_xe, NN, 1);
    }
    cudaEventRecord(evXe, s1);

    {   // xw1 = x @ W1 (two 64-col blocks) on the main stream
        dim3 grid(2, (NN + BMT - 1) / BMT);
        bf16_fused_gemm_kernel<<<grid, 256, SMEM_BYTES>>>(x, W1, Wx, bx, p_xw1, p_xe, NN, 0);
    }
    cudaStreamWaitEvent(0, evDeg, 0);

    init_agg1_kernel<<<(NN * (HH / 4) + T - 1) / T, T>>>(b1);
    {   // layer-1 scatter: one warp per edge, 4 edges/warp
        int warps = (EE + 3) / 4;
        int blocks = (warps * 32 + T - 1) / T;
        scatter1_kernel<<<blocks, T>>>(ei, ei + EE);
    }

    {   // xw2 = relu(agg1) @ W2 — relu fused into A load
        dim3 grid(CC / 16, (NN + 127) / 128);
        sgemm_kernel<128, 16, 16, 8, 2, true, 2><<<grid, 128>>>(p_agg1, W2, nullptr, p_xw2, NN, CC, HH, 0);
    }
    init_agg2_kernel<<<(NN * (CC / 4) + T - 1) / T, T>>>(b2);
    scatter2_kernel<<<(EE * 4 + T - 1) / T, T>>>(ei, ei + EE);

    cudaStreamWaitEvent(0, evXe, 0);
    node_kernel<<<(NN + T - 1) / T, T>>>(y, tm, Wd, out + 2 * (size_t)EE);
    decode_kernel<<<(2 * EE + T - 1) / T, T>>>(ei, nei, bd, out);
}

// round 17
// speedup vs baseline: 1.3239x; 1.0002x over previous
#include <cuda_runtime.h>
#include <math.h>
#include <stdint.h>

#define NN  50000
#define FF  256
#define HH  128
#define CC  16
#define HXD 64
#define EE  500000

// ---------------- scratch (device globals; no allocation allowed) ----------------
__device__ float g_xw1 [(size_t)NN * HH];   // x @ W1
__device__ float g_xe  [(size_t)NN * HXD];  // relu(x @ Wx + bx)
__device__ float g_agg1[(size_t)NN * HH];   // layer-1 aggregate (relu fused into GEMM2 load)
__device__ float g_xw2 [(size_t)NN * CC];   // h @ W2
__device__ float g_agg2[(size_t)NN * CC];   // layer-2 aggregate = logits
__device__ float g_deg [NN];
__device__ float g_norm[EE];
__device__ float g_u   [NN];
__device__ float g_v   [NN];
__device__ int   g_maskkind;                // 0=int32, 1=float32, 2=byte/bool

// ---------------- prep: deg=1 (self loop) + train_mask dtype detection ----------------
__global__ void prep_kernel(const unsigned* __restrict__ tm) {
    int i = blockIdx.x * blockDim.x + threadIdx.x;
    if (i < NN) g_deg[i] = 1.0f;
    if (blockIdx.x == 0) {
        __shared__ int bad_int, bad_float;
        if (threadIdx.x == 0) { bad_int = 0; bad_float = 0; }
        __syncthreads();
        for (int j = threadIdx.x; j < 2048; j += blockDim.x) {
            unsigned v = tm[j];
            if (v > 1u) bad_int = 1;                          // benign write race
            if (v != 0u && v != 0x3F800000u) bad_float = 1;
        }
        __syncthreads();
        if (threadIdx.x == 0)
            g_maskkind = (bad_int == 0) ? 0 : ((bad_float == 0) ? 1 : 2);
    }
}

__global__ void deg_count_kernel(const int* __restrict__ dst) {
    int e = blockIdx.x * blockDim.x + threadIdx.x;
    if (e < EE) atomicAdd(&g_deg[dst[e]], 1.0f);
}

__global__ void norm_kernel(const int* __restrict__ src, const int* __restrict__ dst) {
    int e = blockIdx.x * blockDim.x + threadIdx.x;
    if (e < EE) g_norm[e] = rsqrtf(g_deg[src[e]]) * rsqrtf(g_deg[dst[e]]);
}

// ================= fused 3xBF16 tensor-core GEMM (R8 config) =================
// xePart=0: grid.x in {0,1} -> xw1 columns.  xePart=1: this launch computes xe.
#define BMT 128
#define BNT 64
#define BKT 32
#define ARL 20
#define BRL 72
#define A_SZ (BMT * ARL)
#define B_SZ ((BKT / 2) * BRL)
#define BUF_SZ (2 * A_SZ + 2 * B_SZ)
#define SMEM_BYTES (2 * BUF_SZ * 4)

__device__ __forceinline__ void splitpack(float e, float o, uint32_t& hp, uint32_t& lp) {
    asm("cvt.rn.bf16x2.f32 %0, %1, %2;" : "=r"(hp) : "f"(o), "f"(e));
    float he = __uint_as_float(hp << 16);
    float ho = __uint_as_float(hp & 0xFFFF0000u);
    float le = e - he, lo = o - ho;
    asm("cvt.rn.bf16x2.f32 %0, %1, %2;" : "=r"(lp) : "f"(lo), "f"(le));
}

__device__ __forceinline__ void mma_bf16(float* c, const uint32_t* a, const uint32_t* b) {
    asm volatile(
        "mma.sync.aligned.m16n8k16.row.col.f32.bf16.bf16.f32 "
        "{%0,%1,%2,%3}, {%4,%5,%6,%7}, {%8,%9}, {%0,%1,%2,%3};"
        : "+f"(c[0]), "+f"(c[1]), "+f"(c[2]), "+f"(c[3])
        : "r"(a[0]), "r"(a[1]), "r"(a[2]), "r"(a[3]), "r"(b[0]), "r"(b[1]));
}

__global__ __launch_bounds__(256, 2)
void bf16_fused_gemm_kernel(const float* __restrict__ A,
                            const float* __restrict__ W1,
                            const float* __restrict__ Wx,
                            const float* __restrict__ bx,
                            float* __restrict__ Cxw1,
                            float* __restrict__ Cxe,
                            int M, int xePart) {
    extern __shared__ uint32_t sm[];

    const int tid = threadIdx.x;
    const int rowBase = blockIdx.y * BMT;
    const bool isXe = (xePart != 0);
    const float* Bsrc = isXe ? Wx : W1;
    const int Bstride = isXe ? HXD : HH;
    const int colOff = isXe ? 0 : blockIdx.x * BNT;

    const int warp = tid >> 5, lane = tid & 31;
    const int wm = warp >> 1, wn = warp & 1;
    const int lr = lane >> 2, lc = lane & 3;

    float4 aSt[4];
    float2 bSt0[2], bSt1[2];

    auto loadStage = [&](int k0) {
#pragma unroll
        for (int r = 0; r < 4; r++) {
            int i = tid + r * 256;
            int kq = i & 7, m = i >> 3;
            int gr = rowBase + m;
            float4 v = make_float4(0.f, 0.f, 0.f, 0.f);
            if (gr < M) v = *(const float4*)&A[(size_t)gr * FF + k0 + kq * 4];
            aSt[r] = v;
        }
#pragma unroll
        for (int r = 0; r < 2; r++) {
            int u = tid + r * 256;
            int kp = u >> 5, np = u & 31;
            const float* p0 = Bsrc + (size_t)(k0 + 2 * kp) * Bstride + colOff + 2 * np;
            bSt0[r] = *(const float2*)p0;
            bSt1[r] = *(const float2*)(p0 + Bstride);
        }
    };
    auto storeStage = [&](int buf) {
        uint32_t* Ah_ = sm + buf * BUF_SZ;
        uint32_t* Al_ = Ah_ + A_SZ;
        uint32_t* Bh_ = Al_ + A_SZ;
        uint32_t* Bl_ = Bh_ + B_SZ;
#pragma unroll
        for (int r = 0; r < 4; r++) {
            int i = tid + r * 256;
            int kq = i & 7, m = i >> 3;
            uint32_t hp0, lp0, hp1, lp1;
            splitpack(aSt[r].x, aSt[r].y, hp0, lp0);
            splitpack(aSt[r].z, aSt[r].w, hp1, lp1);
            *(uint2*)&Ah_[m * ARL + 2 * kq] = make_uint2(hp0, hp1);
            *(uint2*)&Al_[m * ARL + 2 * kq] = make_uint2(lp0, lp1);
        }
#pragma unroll
        for (int r = 0; r < 2; r++) {
            int u = tid + r * 256;
            int kp = u >> 5, np = u & 31;
            uint32_t hp0, lp0, hp1, lp1;
            splitpack(bSt0[r].x, bSt1[r].x, hp0, lp0);
            splitpack(bSt0[r].y, bSt1[r].y, hp1, lp1);
            *(uint2*)&Bh_[kp * BRL + 2 * np] = make_uint2(hp0, hp1);
            *(uint2*)&Bl_[kp * BRL + 2 * np] = make_uint2(lp0, lp1);
        }
    };

    float acc[2][4][4];
#pragma unroll
    for (int i = 0; i < 2; i++)
#pragma unroll
        for (int j = 0; j < 4; j++)
#pragma unroll
            for (int c = 0; c < 4; c++) acc[i][j][c] = 0.0f;

    const int nTiles = FF / BKT;
    loadStage(0);
    storeStage(0);
    __syncthreads();
    int buf = 0;
    for (int t = 0; t < nTiles; t++) {
        if (t + 1 < nTiles) loadStage((t + 1) * BKT);
        const uint32_t* Ah_ = sm + buf * BUF_SZ;
        const uint32_t* Al_ = Ah_ + A_SZ;
        const uint32_t* Bh_ = Al_ + A_SZ;
        const uint32_t* Bl_ = Bh_ + B_SZ;
#pragma unroll
        for (int kb = 0; kb < 2; kb++) {
            const int kb8 = kb * 8;
            uint32_t fah[2][4], fal[2][4], fbh[4][2], fbl[4][2];
#pragma unroll
            for (int i = 0; i < 2; i++) {
                int row = wm * 32 + i * 16 + lr;
                fah[i][0] = Ah_[row * ARL + kb8 + lc];
                fah[i][1] = Ah_[(row + 8) * ARL + kb8 + lc];
                fah[i][2] = Ah_[row * ARL + kb8 + lc + 4];
                fah[i][3] = Ah_[(row + 8) * ARL + kb8 + lc + 4];
                fal[i][0] = Al_[row * ARL + kb8 + lc];
                fal[i][1] = Al_[(row + 8) * ARL + kb8 + lc];
                fal[i][2] = Al_[row * ARL + kb8 + lc + 4];
                fal[i][3] = Al_[(row + 8) * ARL + kb8 + lc + 4];
            }
#pragma unroll
            for (int j = 0; j < 4; j++) {
                int n = wn * 32 + j * 8 + lr;
                fbh[j][0] = Bh_[(kb8 + lc) * BRL + n];
                fbh[j][1] = Bh_[(kb8 + lc + 4) * BRL + n];
                fbl[j][0] = Bl_[(kb8 + lc) * BRL + n];
                fbl[j][1] = Bl_[(kb8 + lc + 4) * BRL + n];
            }
#pragma unroll
            for (int i = 0; i < 2; i++)
#pragma unroll
                for (int j = 0; j < 4; j++) {
                    mma_bf16(acc[i][j], fah[i], fbh[j]);
                    mma_bf16(acc[i][j], fal[i], fbh[j]);
                    mma_bf16(acc[i][j], fah[i], fbl[j]);
                }
        }
        if (t + 1 < nTiles) storeStage(buf ^ 1);
        __syncthreads();
        buf ^= 1;
    }

#pragma unroll
    for (int i = 0; i < 2; i++) {
        int r0 = rowBase + wm * 32 + i * 16 + lr;
#pragma unroll
        for (int j = 0; j < 4; j++) {
            int gcl = wn * 32 + j * 8 + 2 * lc;
            if (!isXe) {
                int col = blockIdx.x * BNT + gcl;
                if (r0 < M)
                    *(float2*)&Cxw1[(size_t)r0 * HH + col] = make_float2(acc[i][j][0], acc[i][j][1]);
                if (r0 + 8 < M)
                    *(float2*)&Cxw1[(size_t)(r0 + 8) * HH + col] = make_float2(acc[i][j][2], acc[i][j][3]);
            } else {
                float b0 = __ldg(&bx[gcl]), b1 = __ldg(&bx[gcl + 1]);
                if (r0 < M)
                    *(float2*)&Cxe[(size_t)r0 * HXD + gcl] =
                        make_float2(fmaxf(acc[i][j][0] + b0, 0.f), fmaxf(acc[i][j][1] + b1, 0.f));
                if (r0 + 8 < M)
                    *(float2*)&Cxe[(size_t)(r0 + 8) * HXD + gcl] =
                        make_float2(fmaxf(acc[i][j][2] + b0, 0.f), fmaxf(acc[i][j][3] + b1, 0.f));
            }
        }
    }
}

// ---------------- double-buffered (smem only) fp32 GEMM (used for GEMM2) ----------------
template <int BM, int BN, int BK, int TM, int TN, bool RELU_A, int MINB>
__global__ __launch_bounds__((BM / TM) * (BN / TN), MINB)
void sgemm_kernel(const float* __restrict__ A, const float* __restrict__ B,
                  const float* __restrict__ bias, float* __restrict__ C,
                  int M, int N, int K, int doRelu) {
    constexpr int NT = (BM / TM) * (BN / TN);
    constexpr int AV = BM * BK / 4;
    constexpr int BV = BK * BN / 4;
    constexpr int AR = (AV + NT - 1) / NT;
    constexpr int BR = (BV + NT - 1) / NT;
    __shared__ float As[2][BK][BM];
    __shared__ float Bs[2][BK][BN];
    const int tid = threadIdx.x;
    const int tpr = BN / TN;
    const int tr = tid / tpr;
    const int tc = tid % tpr;
    const int rowBase = blockIdx.y * BM;
    const int colBase = blockIdx.x * BN;

    float4 aReg[AR], bReg[BR];

    auto loadTile = [&](int k0) {
#pragma unroll
        for (int r = 0; r < AR; r++) {
            int i = tid + r * NT;
            if ((AV % NT) && i >= AV) continue;
            int kq = i % (BK / 4);
            int m = i / (BK / 4);
            int gr = rowBase + m;
            float4 v = make_float4(0.f, 0.f, 0.f, 0.f);
            if (gr < M) v = *(const float4*)&A[(size_t)gr * K + k0 + kq * 4];
            if (RELU_A) {
                v.x = fmaxf(v.x, 0.f); v.y = fmaxf(v.y, 0.f);
                v.z = fmaxf(v.z, 0.f); v.w = fmaxf(v.w, 0.f);
            }
            aReg[r] = v;
        }
#pragma unroll
        for (int r = 0; r < BR; r++) {
            int i = tid + r * NT;
            if ((BV % NT) && i >= BV) continue;
            int nq = i % (BN / 4);
            int kk = i / (BN / 4);
            bReg[r] = *(const float4*)&B[(size_t)(k0 + kk) * N + colBase + nq * 4];
        }
    };
    auto storeTile = [&](int buf) {
#pragma unroll
        for (int r = 0; r < AR; r++) {
            int i = tid + r * NT;
            if ((AV % NT) && i >= AV) continue;
            int kq = i % (BK / 4);
            int m = i / (BK / 4);
            As[buf][kq * 4 + 0][m] = aReg[r].x;
            As[buf][kq * 4 + 1][m] = aReg[r].y;
            As[buf][kq * 4 + 2][m] = aReg[r].z;
            As[buf][kq * 4 + 3][m] = aReg[r].w;
        }
#pragma unroll
        for (int r = 0; r < BR; r++) {
            int i = tid + r * NT;
            if ((BV % NT) && i >= BV) continue;
            int nq = i % (BN / 4);
            int kk = i / (BN / 4);
            *(float4*)&Bs[buf][kk][nq * 4] = bReg[r];
        }
    };

    float acc[TM][TN];
#pragma unroll
    for (int i = 0; i < TM; i++)
#pragma unroll
        for (int j = 0; j < TN; j++) acc[i][j] = 0.0f;

    const int nTiles = K / BK;
    loadTile(0);
    storeTile(0);
    __syncthreads();
    int buf = 0;
    for (int t = 0; t < nTiles; t++) {
        if (t + 1 < nTiles) loadTile((t + 1) * BK);
#pragma unroll
        for (int kk = 0; kk < BK; kk++) {
            float ra[TM], rb[TN];
#pragma unroll
            for (int i = 0; i < TM; i++) ra[i] = As[buf][kk][tr * TM + i];
#pragma unroll
            for (int j = 0; j < TN; j++) rb[j] = Bs[buf][kk][tc * TN + j];
#pragma unroll
            for (int i = 0; i < TM; i++)
#pragma unroll
                for (int j = 0; j < TN; j++) acc[i][j] += ra[i] * rb[j];
        }
        if (t + 1 < nTiles) storeTile(buf ^ 1);
        __syncthreads();
        buf ^= 1;
    }

#pragma unroll
    for (int i = 0; i < TM; i++) {
        int gr = rowBase + tr * TM + i;
        if (gr >= M) continue;
#pragma unroll
        for (int j = 0; j < TN; j++) {
            int gc = colBase + tc * TN + j;
            float val = acc[i][j] + (bias ? bias[gc] : 0.0f);
            if (doRelu) val = fmaxf(val, 0.0f);
            C[(size_t)gr * N + gc] = val;
        }
    }
}

// ---------------- layer-1 aggregation (RED-based, R8 structure) ----------------
__global__ void init_agg1_kernel(const float* __restrict__ b1) {
    int i = blockIdx.x * blockDim.x + threadIdx.x;     // float4 index
    if (i >= NN * (HH / 4)) return;
    int n = i / (HH / 4);
    int q = i % (HH / 4);
    float di = rsqrtf(g_deg[n]);
    float sc = di * di;
    float4 xv = ((const float4*)g_xw1)[i];
    float4 bv = __ldg(&((const float4*)b1)[q]);
    float4 o;
    o.x = sc * xv.x + bv.x; o.y = sc * xv.y + bv.y;
    o.z = sc * xv.z + bv.z; o.w = sc * xv.w + bv.w;
    ((float4*)g_agg1)[i] = o;
}

__global__ void scatter1_kernel(const int* __restrict__ src, const int* __restrict__ dst) {
    const int EPW = 4;  // edges per warp
    int w = (blockIdx.x * blockDim.x + threadIdx.x) >> 5;
    int lane = threadIdx.x & 31;
    int e0 = w * EPW;
    int e1 = e0 + EPW; if (e1 > EE) e1 = EE;
    for (int e = e0; e < e1; e++) {
        int s = __ldg(&src[e]);
        int d = __ldg(&dst[e]);
        float nm = g_norm[e];
        float4 v = *(const float4*)&g_xw1[(size_t)s * HH + lane * 4];
        float* p = &g_agg1[(size_t)d * HH + lane * 4];
        asm volatile("red.global.add.v4.f32 [%0], {%1,%2,%3,%4};"
                     :: "l"(p), "f"(nm * v.x), "f"(nm * v.y), "f"(nm * v.z), "f"(nm * v.w)
                     : "memory");
    }
}

// ---------------- layer-2 aggregation ----------------
__global__ void init_agg2_kernel(const float* __restrict__ b2) {
    int i = blockIdx.x * blockDim.x + threadIdx.x;     // float4 index
    if (i >= NN * (CC / 4)) return;
    int n = i / (CC / 4);
    int q = i % (CC / 4);
    float di = rsqrtf(g_deg[n]);
    float sc = di * di;
    float4 xv = ((const float4*)g_xw2)[i];
    float4 bv = __ldg(&((const float4*)b2)[q]);
    float4 o;
    o.x = sc * xv.x + bv.x; o.y = sc * xv.y + bv.y;
    o.z = sc * xv.z + bv.z; o.w = sc * xv.w + bv.w;
    ((float4*)g_agg2)[i] = o;
}

__global__ void scatter2_kernel(const int* __restrict__ src, const int* __restrict__ dst) {
    int gt = blockIdx.x * blockDim.x + threadIdx.x;
    int e = gt >> 2;          // 4 threads per edge (16 floats)
    int q = gt & 3;
    if (e >= EE) return;
    int s = __ldg(&src[e]);
    int d = __ldg(&dst[e]);
    float nm = g_norm[e];
    float4 v = ((const float4*)&g_xw2[(size_t)s * CC])[q];
    float* p = &g_agg2[(size_t)d * CC + q * 4];
    asm volatile("red.global.add.v4.f32 [%0], {%1,%2,%3,%4};"
                 :: "l"(p), "f"(nm * v.x), "f"(nm * v.y), "f"(nm * v.z), "f"(nm * v.w)
                 : "memory");
}

// ---------------- u/v xe-part: u0 = xe . Wd[0:64], v0 = xe . Wd[64:128] ----------------
__global__ void uv_xe_kernel(const float* __restrict__ Wd) {
    int n = blockIdx.x * blockDim.x + threadIdx.x;
    if (n >= NN) return;
    float u = 0.0f, v = 0.0f;
    const float4* xr = (const float4*)&g_xe[(size_t)n * HXD];
#pragma unroll
    for (int k4 = 0; k4 < HXD / 4; k4++) {
        float4 xv = xr[k4];
        int k = k4 * 4;
        u += xv.x * __ldg(&Wd[k + 0]) + xv.y * __ldg(&Wd[k + 1])
           + xv.z * __ldg(&Wd[k + 2]) + xv.w * __ldg(&Wd[k + 3]);
        v += xv.x * __ldg(&Wd[64 + k + 0]) + xv.y * __ldg(&Wd[64 + k + 1])
           + xv.z * __ldg(&Wd[64 + k + 2]) + xv.w * __ldg(&Wd[64 + k + 3]);
    }
    g_u[n] = u;
    g_v[n] = v;
}

// ---------------- per-node: log_softmax, y_prob contribution to u/v ----------------
__global__ void node_kernel(const int* __restrict__ y, const void* __restrict__ tmask,
                            const float* __restrict__ Wd, float* __restrict__ out_lsm) {
    int n = blockIdx.x * blockDim.x + threadIdx.x;
    if (n >= NN) return;
    float l[CC];
    const float* lr = &g_agg2[(size_t)n * CC];
    float m = -1e30f;
#pragma unroll
    for (int c = 0; c < CC; c++) { l[c] = lr[c]; m = fmaxf(m, l[c]); }
    float se = 0.0f;
#pragma unroll
    for (int c = 0; c < CC; c++) se += expf(l[c] - m);
    float lse = logf(se);

    int kind = g_maskkind;
    bool msk;
    if (kind == 0)      msk = ((const int*)tmask)[n] != 0;
    else if (kind == 1) msk = ((const float*)tmask)[n] != 0.0f;
    else                msk = ((const unsigned char*)tmask)[n] != 0;
    int yc = y[n];

    float u = g_u[n], v = g_v[n];
#pragma unroll
    for (int c = 0; c < CC; c++) {
        float lsm = l[c] - m - lse;
        out_lsm[(size_t)n * CC + c] = lsm;
        float yp = msk ? ((c == yc) ? 1.0f : 0.0f) : expf(lsm);
        u += yp * __ldg(&Wd[128 + c]);
        v += yp * __ldg(&Wd[144 + c]);
    }
    g_u[n] = u;
    g_v[n] = v;
}

// ---------------- edge decode ----------------
__global__ void decode_kernel(const int* __restrict__ pos, const int* __restrict__ neg,
                              const float* __restrict__ bd, float* __restrict__ out) {
    int i = blockIdx.x * blockDim.x + threadIdx.x;
    if (i >= 2 * EE) return;
    const int* ei = (i < EE) ? pos : neg;
    int k = (i < EE) ? i : i - EE;
    int s = ei[k];
    int d = ei[EE + k];
    out[i] = g_u[s] + g_v[d] + __ldg(bd);
}

// ---------------- launch ----------------
extern "C" void kernel_launch(void* const* d_in, const int* in_sizes, int n_in,
                              void* d_out, int out_size) {
    const float* x  = (const float*)d_in[0];
    const int* ei   = (const int*)d_in[1];   // [2, E] row-major: src then dst
    const int* nei  = (const int*)d_in[2];
    const int* y    = (const int*)d_in[3];
    const void* tm  = d_in[4];
    const float* W1 = (const float*)d_in[5];
    const float* b1 = (const float*)d_in[6];
    const float* W2 = (const float*)d_in[7];
    const float* b2 = (const float*)d_in[8];
    const float* Wx = (const float*)d_in[9];
    const float* bx = (const float*)d_in[10];
    const float* Wd = (const float*)d_in[11];
    const float* bd = (const float*)d_in[12];
    float* out = (float*)d_out;

    float *p_xw1, *p_xe, *p_agg1, *p_xw2;
    cudaGetSymbolAddress((void**)&p_xw1, g_xw1);
    cudaGetSymbolAddress((void**)&p_xe, g_xe);
    cudaGetSymbolAddress((void**)&p_agg1, g_agg1);
    cudaGetSymbolAddress((void**)&p_xw2, g_xw2);

    static cudaStream_t s1 = nullptr;
    static cudaEvent_t evFork = nullptr, evDeg = nullptr, evUV = nullptr;
    if (!s1) {
        int loPri, hiPri;
        cudaDeviceGetStreamPriorityRange(&loPri, &hiPri);   // loPri = lowest priority
        cudaStreamCreateWithPriority(&s1, cudaStreamNonBlocking, loPri);
        cudaEventCreateWithFlags(&evFork, cudaEventDisableTiming);
        cudaEventCreateWithFlags(&evDeg, cudaEventDisableTiming);
        cudaEventCreateWithFlags(&evUV, cudaEventDisableTiming);
        cudaFuncSetAttribute(bf16_fused_gemm_kernel,
                             cudaFuncAttributeMaxDynamicSharedMemorySize, SMEM_BYTES);
    }

    const int T = 256;

    prep_kernel<<<(NN + T - 1) / T, T>>>((const unsigned*)tm);
    cudaEventRecord(evFork, 0);
    cudaStreamWaitEvent(s1, evFork, 0);

    // low-priority side stream: degree + norm, xe-GEMM, and the xe-part of u/v
    deg_count_kernel<<<(EE + T - 1) / T, T, 0, s1>>>(ei + EE);
    norm_kernel<<<(EE + T - 1) / T, T, 0, s1>>>(ei, ei + EE);
    cudaEventRecord(evDeg, s1);
    {   // xe = relu(x @ Wx + bx)  (fills gaps; drains under scatter1)
        dim3 grid(1, (NN + BMT - 1) / BMT);
        bf16_fused_gemm_kernel<<<grid, 256, SMEM_BYTES, s1>>>(x, W1, Wx, bx, p_xw1, p_xe, NN, 1);
    }
    uv_xe_kernel<<<(NN + T - 1) / T, T, 0, s1>>>(Wd);
    cudaEventRecord(evUV, s1);

    {   // xw1 = x @ W1 (two 64-col blocks) on the high-priority main stream
        dim3 grid(2, (NN + BMT - 1) / BMT);
        bf16_fused_gemm_kernel<<<grid, 256, SMEM_BYTES>>>(x, W1, Wx, bx, p_xw1, p_xe, NN, 0);
    }
    cudaStreamWaitEvent(0, evDeg, 0);

    init_agg1_kernel<<<(NN * (HH / 4) + T - 1) / T, T>>>(b1);
    {   // layer-1 scatter: one warp per edge, 4 edges/warp
        int warps = (EE + 3) / 4;
        int blocks = (warps * 32 + T - 1) / T;
        scatter1_kernel<<<blocks, T>>>(ei, ei + EE);
    }

    {   // xw2 = relu(agg1) @ W2 — relu fused into A load
        dim3 grid(CC / 16, (NN + 127) / 128);
        sgemm_kernel<128, 16, 16, 8, 2, true, 2><<<grid, 128>>>(p_agg1, W2, nullptr, p_xw2, NN, CC, HH, 0);
    }
    init_agg2_kernel<<<(NN * (CC / 4) + T - 1) / T, T>>>(b2);
    scatter2_kernel<<<(EE * 4 + T - 1) / T, T>>>(ei, ei + EE);

    cudaStreamWaitEvent(0, evUV, 0);
    node_kernel<<<(NN + T - 1) / T, T>>>(y, tm, Wd, out + 2 * (size_t)EE);
    decode_kernel<<<(2 * EE + T - 1) / T, T>>>(ei, nei, bd, out);
}